// round 1
// baseline (speedup 1.0000x reference)
#include <cuda_runtime.h>
#include <math.h>

#define BB 8
#define NN 8192
#define DXc 2
#define EE 128
#define HH 8
#define HDc 16
#define KHc 32
#define FFc 128
#define G1 32
#define G2 32
#define PP 32
#define MM (G1*G2)      // 1024
#define TT (BB*MM)      // 8192

// ---------------- device scratch (no allocations allowed) ----------------
__device__ float g_min[2];
__device__ float g_max[2];
__device__ int   g_count[TT];
__device__ int   g_ptid[TT*PP];
__device__ float g_qWk[EE*HH];   // qWk[e][h] = sum_d q[h*16+d] * Wk[e][h*16+d]
__device__ float g_v0[EE];       // value vector of the grid token (constant)
__device__ float g_dots0[HH];    // logit of the grid token (constant)

// ---------------- helpers ----------------
__device__ __forceinline__ void atomicMinF(float* addr, float v){
  if (v >= 0.f) atomicMin((int*)addr, __float_as_int(v));
  else          atomicMax((unsigned int*)addr, __float_as_uint(v));
}
__device__ __forceinline__ void atomicMaxF(float* addr, float v){
  if (v >= 0.f) atomicMax((int*)addr, __float_as_int(v));
  else          atomicMin((unsigned int*)addr, __float_as_uint(v));
}

// ---------------- kernel 0: init counters + minmax ----------------
__global__ void k_init(){
  int i = blockIdx.x*blockDim.x + threadIdx.x;
  if (i < TT) g_count[i] = 0;
  if (i < 2){
    g_min[i] = __int_as_float(0x7f800000);   // +inf
    g_max[i] = __int_as_float(0xff800000);   // -inf
  }
}

// ---------------- kernel 1: global min/max of x per dim ----------------
__global__ void k_minmax(const float* __restrict__ x){
  float mn0=1e38f, mn1=1e38f, mx0=-1e38f, mx1=-1e38f;
  for (int i = blockIdx.x*blockDim.x + threadIdx.x; i < BB*NN; i += gridDim.x*blockDim.x){
    float2 v = ((const float2*)x)[i];
    mn0 = fminf(mn0, v.x); mx0 = fmaxf(mx0, v.x);
    mn1 = fminf(mn1, v.y); mx1 = fmaxf(mx1, v.y);
  }
  #pragma unroll
  for (int o=16;o;o>>=1){
    mn0 = fminf(mn0, __shfl_xor_sync(0xffffffffu, mn0, o));
    mx0 = fmaxf(mx0, __shfl_xor_sync(0xffffffffu, mx0, o));
    mn1 = fminf(mn1, __shfl_xor_sync(0xffffffffu, mn1, o));
    mx1 = fmaxf(mx1, __shfl_xor_sync(0xffffffffu, mx1, o));
  }
  __shared__ float s[4][8];
  int w = threadIdx.x>>5, l = threadIdx.x&31;
  if (l==0){ s[0][w]=mn0; s[1][w]=mx0; s[2][w]=mn1; s[3][w]=mx1; }
  __syncthreads();
  if (threadIdx.x==0){
    int nw = blockDim.x>>5;
    float a=s[0][0], b=s[1][0], c=s[2][0], d=s[3][0];
    for (int j=1;j<nw;j++){ a=fminf(a,s[0][j]); b=fmaxf(b,s[1][j]); c=fminf(c,s[2][j]); d=fmaxf(d,s[3][j]); }
    atomicMinF(&g_min[0], a); atomicMaxF(&g_max[0], b);
    atomicMinF(&g_min[1], c); atomicMaxF(&g_max[1], d);
  }
}

// ---------------- kernel 2: precompute q-folded Wk, grid-token constants ----------------
__global__ void k_prep(const float* __restrict__ latent,
                       const float* __restrict__ Wq, const float* __restrict__ Wk,
                       const float* __restrict__ Wv,
                       const float* __restrict__ lnq_g, const float* __restrict__ lnq_b,
                       const float* __restrict__ lnk_g, const float* __restrict__ lnk_b,
                       const float* __restrict__ kb1, const float* __restrict__ kW2,
                       const float* __restrict__ kb2){
  __shared__ float s_lnq[EE], s_lnk[EE], s_q[EE], s_red[4];
  int tid = threadIdx.x, lane = tid&31, warp = tid>>5;
  float v = latent[tid];
  // block mean
  float sv = v;
  #pragma unroll
  for (int o=16;o;o>>=1) sv += __shfl_xor_sync(0xffffffffu, sv, o);
  if (lane==0) s_red[warp]=sv;
  __syncthreads();
  float mu = (s_red[0]+s_red[1]+s_red[2]+s_red[3]) * (1.f/EE);
  float d = v - mu;
  float qv = d*d;
  #pragma unroll
  for (int o=16;o;o>>=1) qv += __shfl_xor_sync(0xffffffffu, qv, o);
  __syncthreads();
  if (lane==0) s_red[warp]=qv;
  __syncthreads();
  float var = (s_red[0]+s_red[1]+s_red[2]+s_red[3]) * (1.f/EE);
  float rs = rsqrtf(var + 1e-5f);
  s_lnq[tid] = d*rs*lnq_g[tid] + lnq_b[tid];
  s_lnk[tid] = d*rs*lnk_g[tid] + lnk_b[tid];
  __syncthreads();
  // qvec[f] and v0[f]
  float accq = 0.f, accv = 0.f;
  for (int e=0;e<EE;e++){
    accq += s_lnq[e]*Wq[e*EE+tid];
    accv += s_lnk[e]*Wv[e*EE+tid];
  }
  s_q[tid] = accq;
  g_v0[tid] = accv;
  __syncthreads();
  // qWk[e=tid][h]
  for (int h=0; h<HH; h++){
    float a = 0.f;
    #pragma unroll
    for (int dd=0; dd<HDc; dd++) a += s_q[h*HDc+dd]*Wk[tid*EE + h*HDc + dd];
    g_qWk[tid*HH + h] = a;
  }
  __syncthreads();
  if (tid < HH){
    float a = 0.f;
    for (int e=0;e<EE;e++) a += s_lnk[e]*g_qWk[e*HH+tid];
    a *= 0.25f;   // 1/sqrt(16)
    // kernel-bias MLP for diff = 0: hidden = relu(kb1)
    float kb = kb2[tid];
    for (int j=0;j<KHc;j++){
      float hv = kb1[j];
      if (hv > 0.f) kb += hv*kW2[j*HH+tid];
    }
    g_dots0[tid] = a + kb;
  }
}

// ---------------- kernel 3: bin points into grid cells ----------------
__global__ void k_bin(const float* __restrict__ x){
  float mn0=g_min[0], mx0=g_max[0], mn1=g_min[1], mx1=g_max[1];
  float st0 = __fdiv_rn(mx0-mn0, (float)(G1-1));
  float st1 = __fdiv_rn(mx1-mn1, (float)(G2-1));
  for (int i = blockIdx.x*blockDim.x + threadIdx.x; i < BB*NN; i += gridDim.x*blockDim.x){
    float2 v = ((const float2*)x)[i];
    float f0 = rintf(__fdiv_rn(v.x-mn0, st0));
    float f1 = rintf(__fdiv_rn(v.y-mn1, st1));
    f0 = fminf(fmaxf(f0, 0.f), (float)(G1-1));
    f1 = fminf(fmaxf(f1, 0.f), (float)(G2-1));
    int i0 = (int)f0, i1 = (int)f1;
    int b = i / NN, n = i % NN;
    int t = b*MM + i0*G2 + i1;
    int slot = atomicAdd(&g_count[t], 1);
    if (slot < PP) g_ptid[t*PP + slot] = n;
  }
}

// ---------------- kernel 4: main fused token kernel ----------------
__global__ void __launch_bounds__(128) k_main(
    const float* __restrict__ x, const float* __restrict__ z,
    const float* __restrict__ latent,
    const float* __restrict__ Wv, const float* __restrict__ Wo, const float* __restrict__ bo,
    const float* __restrict__ kW1, const float* __restrict__ kb1,
    const float* __restrict__ kW2, const float* __restrict__ kb2,
    const float* __restrict__ lnk_g, const float* __restrict__ lnk_b,
    const float* __restrict__ ln2_g, const float* __restrict__ ln2_b,
    const float* __restrict__ fW1, const float* __restrict__ fb1,
    const float* __restrict__ fW2, const float* __restrict__ fb2,
    float* __restrict__ out_x, float* __restrict__ out_z)
{
  __shared__ float s_zk[PP][EE];
  __shared__ float s_v[PP][EE];
  __shared__ float s_jx[PP][2];
  __shared__ float s_dots[HH][PP+1];
  __shared__ float s_rsum[HH];
  __shared__ float s_out[EE];
  __shared__ float s_znew[EE];
  __shared__ float s_ln2[EE];
  __shared__ float s_h1[FFc];
  __shared__ float s_red[4];

  int t = blockIdx.x;
  int b = t >> 10;
  int cell = t & (MM-1);
  int c1 = cell >> 5, c2 = cell & 31;
  int tid = threadIdx.x;
  int lane = tid & 31, warp = tid >> 5;

  int cnt = g_count[t]; if (cnt > PP) cnt = PP;

  float mn0=g_min[0], mx0=g_max[0], mn1=g_min[1], mx1=g_max[1];
  float st0 = __fdiv_rn(mx0-mn0, (float)(G1-1));
  float st1 = __fdiv_rn(mx1-mn1, (float)(G2-1));
  float xg0 = (c1==G1-1) ? mx0 : (mn0 + (float)c1*st0);
  float xg1 = (c2==G2-1) ? mx1 : (mn1 + (float)c2*st1);

  // ---- phase 1: gather z rows, LayerNorm (one warp per key) ----
  {
    float lg0=lnk_g[lane],    lg1=lnk_g[lane+32], lg2=lnk_g[lane+64], lg3=lnk_g[lane+96];
    float lb0=lnk_b[lane],    lb1=lnk_b[lane+32], lb2=lnk_b[lane+64], lb3=lnk_b[lane+96];
    for (int k = warp; k < cnt; k += 4){
      int n = g_ptid[t*PP + k];
      const float* zr = z + ((size_t)(b*NN + n))*EE;
      float z0=zr[lane], z1=zr[lane+32], z2=zr[lane+64], z3=zr[lane+96];
      float s = z0+z1+z2+z3;
      #pragma unroll
      for (int o=16;o;o>>=1) s += __shfl_xor_sync(0xffffffffu, s, o);
      float mu = s*(1.f/EE);
      float d0=z0-mu, d1=z1-mu, d2=z2-mu, d3=z3-mu;
      float q = d0*d0 + d1*d1 + d2*d2 + d3*d3;
      #pragma unroll
      for (int o=16;o;o>>=1) q += __shfl_xor_sync(0xffffffffu, q, o);
      float rs = rsqrtf(q*(1.f/EE) + 1e-5f);
      s_zk[k][lane]    = d0*rs*lg0 + lb0;
      s_zk[k][lane+32] = d1*rs*lg1 + lb1;
      s_zk[k][lane+64] = d2*rs*lg2 + lb2;
      s_zk[k][lane+96] = d3*rs*lg3 + lb3;
      if (lane < 2) s_jx[k][lane] = x[((size_t)(b*NN+n))*2 + lane];
    }
  }
  __syncthreads();

  // ---- phase 2a: V projection (thread = output feature f, 8-key register tile) ----
  for (int k0 = 0; k0 < cnt; k0 += 8){
    float acc[8] = {0.f,0.f,0.f,0.f,0.f,0.f,0.f,0.f};
    int kmax = cnt - k0; if (kmax > 8) kmax = 8;
    for (int e = 0; e < EE; e++){
      float wv = Wv[e*EE + tid];
      #pragma unroll
      for (int j = 0; j < 8; j++)
        if (j < kmax) acc[j] += s_zk[k0+j][e]*wv;
    }
    for (int j = 0; j < kmax; j++) s_v[k0+j][tid] = acc[j];
  }

  // ---- phase 2b: logits (q-folded) + kernel-bias MLP ----
  for (int p = tid; p < cnt*HH; p += 128){
    int k = p >> 3, h = p & 7;
    float a = 0.f;
    for (int e = 0; e < EE; e++) a += s_zk[k][e]*g_qWk[e*HH + h];
    a *= 0.25f;
    float dx0 = s_jx[k][0]-xg0, dx1 = s_jx[k][1]-xg1;
    float kb = kb2[h];
    for (int j = 0; j < KHc; j++){
      float hv = dx0*kW1[j] + dx1*kW1[KHc + j] + kb1[j];
      if (hv > 0.f) kb += hv*kW2[j*HH + h];
    }
    s_dots[h][k+1] = a + kb;
  }
  if (tid < HH) s_dots[tid][0] = g_dots0[tid];
  __syncthreads();

  // ---- phase 3: softmax per head over cnt+1 keys ----
  if (tid < HH){
    int K = cnt + 1;
    float m = -1e30f;
    for (int k=0;k<K;k++) m = fmaxf(m, s_dots[tid][k]);
    float ssum = 0.f;
    for (int k=0;k<K;k++){
      float e2 = expf(s_dots[tid][k] - m);
      s_dots[tid][k] = e2;
      ssum += e2;
    }
    s_rsum[tid] = 1.f/ssum;
  }
  __syncthreads();

  // ---- phase 4: attention output ----
  {
    int h = tid >> 4;
    float r = s_rsum[h];
    float acc = s_dots[h][0]*g_v0[tid];
    for (int k=0;k<cnt;k++) acc += s_dots[h][k+1]*s_v[k][tid];
    s_out[tid] = acc*r;
  }
  __syncthreads();

  // ---- phase 5: z_new = latent + out@Wo + bo ; LN2 ----
  float zn;
  {
    float acc = 0.f;
    for (int f=0; f<EE; f++) acc += s_out[f]*Wo[f*EE + tid];
    zn = latent[tid] + acc + bo[tid];
    s_znew[tid] = zn;
  }
  {
    float sv = zn;
    #pragma unroll
    for (int o=16;o;o>>=1) sv += __shfl_xor_sync(0xffffffffu, sv, o);
    if (lane==0) s_red[warp] = sv;
    __syncthreads();
    float mu = (s_red[0]+s_red[1]+s_red[2]+s_red[3])*(1.f/EE);
    float dd = zn - mu;
    float qv = dd*dd;
    #pragma unroll
    for (int o=16;o;o>>=1) qv += __shfl_xor_sync(0xffffffffu, qv, o);
    __syncthreads();
    if (lane==0) s_red[warp] = qv;
    __syncthreads();
    float var = (s_red[0]+s_red[1]+s_red[2]+s_red[3])*(1.f/EE);
    s_ln2[tid] = dd*rsqrtf(var+1e-5f)*ln2_g[tid] + ln2_b[tid];
  }
  __syncthreads();

  // ---- phase 6: FFN hidden ----
  {
    float h1 = fb1[tid];
    for (int e=0;e<EE;e++) h1 += s_ln2[e]*fW1[e*FFc + tid];
    s_h1[tid] = fmaxf(h1, 0.f);
  }
  __syncthreads();

  // ---- phase 7: FFN out + residual -> z output ----
  {
    float acc = fb2[tid];
    for (int j=0;j<FFc;j++) acc += s_h1[j]*fW2[j*EE + tid];
    out_z[(size_t)t*EE + tid] = s_znew[tid] + acc;
  }

  // ---- phase 8: TE location update ----
  if (tid < 2){
    float acc = 0.f;
    for (int k=0;k<=cnt;k++){
      float ma = 0.f;
      #pragma unroll
      for (int h=0;h<HH;h++) ma += s_dots[h][k]*s_rsum[h];
      ma *= 0.125f;
      float xv = (k==0) ? ((tid==0)?xg0:xg1) : s_jx[k-1][tid];
      acc += ma*xv;
    }
    out_x[(size_t)t*2 + tid] = acc;
  }
}

// ---------------- launch ----------------
extern "C" void kernel_launch(void* const* d_in, const int* in_sizes, int n_in,
                              void* d_out, int out_size){
  const float* x     = (const float*)d_in[0];
  const float* z     = (const float*)d_in[1];
  const float* latent= (const float*)d_in[6];
  const float* Wq    = (const float*)d_in[7];
  const float* Wk    = (const float*)d_in[8];
  const float* Wv    = (const float*)d_in[9];
  const float* Wo    = (const float*)d_in[10];
  const float* bo    = (const float*)d_in[11];
  const float* kW1   = (const float*)d_in[12];
  const float* kb1   = (const float*)d_in[13];
  const float* kW2   = (const float*)d_in[14];
  const float* kb2   = (const float*)d_in[15];
  const float* lnq_g = (const float*)d_in[16];
  const float* lnq_b = (const float*)d_in[17];
  const float* lnk_g = (const float*)d_in[18];
  const float* lnk_b = (const float*)d_in[19];
  const float* ln2_g = (const float*)d_in[20];
  const float* ln2_b = (const float*)d_in[21];
  const float* fW1   = (const float*)d_in[22];
  const float* fb1   = (const float*)d_in[23];
  const float* fW2   = (const float*)d_in[24];
  const float* fb2   = (const float*)d_in[25];

  float* out   = (float*)d_out;
  float* out_x = out;                       // [B,32,32,2] flattened
  float* out_z = out + (size_t)TT*DXc;      // [B,32,32,128] flattened

  k_init<<<(TT+255)/256, 256>>>();
  k_minmax<<<256, 256>>>(x);
  k_prep<<<1, 128>>>(latent, Wq, Wk, Wv, lnq_g, lnq_b, lnk_g, lnk_b, kb1, kW2, kb2);
  k_bin<<<128, 512>>>(x);
  k_main<<<TT, 128>>>(x, z, latent, Wv, Wo, bo, kW1, kb1, kW2, kb2,
                      lnk_g, lnk_b, ln2_g, ln2_b, fW1, fb1, fW2, fb2,
                      out_x, out_z);
}

// round 2
// speedup vs baseline: 1.7905x; 1.7905x over previous
#include <cuda_runtime.h>
#include <math.h>

#define BB 8
#define NN 8192
#define DXc 2
#define EE 128
#define HH 8
#define HDc 16
#define KHc 32
#define FFc 128
#define G1 32
#define G2 32
#define PP 32
#define MM (G1*G2)      // 1024
#define TT (BB*MM)      // 8192
#define TB 8            // tokens per block in main kernel

// ---------------- device scratch ----------------
__device__ float g_min[2];
__device__ float g_max[2];
__device__ int   g_count[TT];
__device__ int   g_ptid[TT*PP];
__device__ float g_qWkT[HH*EE];  // [h][e]: q-folded Wk
__device__ float g_lnk[EE];      // LN_k(latent)
__device__ float g_dots0[HH];    // grid-token logit (constant)

// ---------------- helpers ----------------
__device__ __forceinline__ void atomicMinF(float* addr, float v){
  if (v >= 0.f) atomicMin((int*)addr, __float_as_int(v));
  else          atomicMax((unsigned int*)addr, __float_as_uint(v));
}
__device__ __forceinline__ void atomicMaxF(float* addr, float v){
  if (v >= 0.f) atomicMax((int*)addr, __float_as_int(v));
  else          atomicMin((unsigned int*)addr, __float_as_uint(v));
}

// ---------------- kernel 0: init counters + minmax sentinels ----------------
__global__ void k_init(){
  int i = blockIdx.x*blockDim.x + threadIdx.x;
  if (i < TT) g_count[i] = 0;
  if (i < 2){
    g_min[i] = __int_as_float(0x7f800000);
    g_max[i] = __int_as_float(0xff800000);
  }
}

// ---------------- kernel 1: global min/max ----------------
__global__ void k_minmax(const float* __restrict__ x){
  float mn0=1e38f, mn1=1e38f, mx0=-1e38f, mx1=-1e38f;
  for (int i = blockIdx.x*blockDim.x + threadIdx.x; i < BB*NN; i += gridDim.x*blockDim.x){
    float2 v = ((const float2*)x)[i];
    mn0 = fminf(mn0, v.x); mx0 = fmaxf(mx0, v.x);
    mn1 = fminf(mn1, v.y); mx1 = fmaxf(mx1, v.y);
  }
  #pragma unroll
  for (int o=16;o;o>>=1){
    mn0 = fminf(mn0, __shfl_xor_sync(0xffffffffu, mn0, o));
    mx0 = fmaxf(mx0, __shfl_xor_sync(0xffffffffu, mx0, o));
    mn1 = fminf(mn1, __shfl_xor_sync(0xffffffffu, mn1, o));
    mx1 = fmaxf(mx1, __shfl_xor_sync(0xffffffffu, mx1, o));
  }
  __shared__ float s[4][8];
  int w = threadIdx.x>>5, l = threadIdx.x&31;
  if (l==0){ s[0][w]=mn0; s[1][w]=mx0; s[2][w]=mn1; s[3][w]=mx1; }
  __syncthreads();
  if (threadIdx.x==0){
    int nw = blockDim.x>>5;
    float a=s[0][0], b=s[1][0], c=s[2][0], d=s[3][0];
    for (int j=1;j<nw;j++){ a=fminf(a,s[0][j]); b=fmaxf(b,s[1][j]); c=fminf(c,s[2][j]); d=fmaxf(d,s[3][j]); }
    atomicMinF(&g_min[0], a); atomicMaxF(&g_max[0], b);
    atomicMinF(&g_min[1], c); atomicMaxF(&g_max[1], d);
  }
}

// ---------------- kernel 2: precompute q-folded Wk, LN_k(latent), dots0 ----------------
__global__ void k_prep(const float* __restrict__ latent,
                       const float* __restrict__ Wq, const float* __restrict__ Wk,
                       const float* __restrict__ lnq_g, const float* __restrict__ lnq_b,
                       const float* __restrict__ lnk_g, const float* __restrict__ lnk_b,
                       const float* __restrict__ kb1, const float* __restrict__ kW2,
                       const float* __restrict__ kb2){
  __shared__ float s_lnq[EE], s_lnk[EE], s_q[EE], s_red[4];
  int tid = threadIdx.x, lane = tid&31, warp = tid>>5;
  float v = latent[tid];
  float sv = v;
  #pragma unroll
  for (int o=16;o;o>>=1) sv += __shfl_xor_sync(0xffffffffu, sv, o);
  if (lane==0) s_red[warp]=sv;
  __syncthreads();
  float mu = (s_red[0]+s_red[1]+s_red[2]+s_red[3]) * (1.f/EE);
  float d = v - mu;
  float qv = d*d;
  #pragma unroll
  for (int o=16;o;o>>=1) qv += __shfl_xor_sync(0xffffffffu, qv, o);
  __syncthreads();
  if (lane==0) s_red[warp]=qv;
  __syncthreads();
  float var = (s_red[0]+s_red[1]+s_red[2]+s_red[3]) * (1.f/EE);
  float rs = rsqrtf(var + 1e-5f);
  s_lnq[tid] = d*rs*lnq_g[tid] + lnq_b[tid];
  float lk = d*rs*lnk_g[tid] + lnk_b[tid];
  s_lnk[tid] = lk;
  g_lnk[tid] = lk;
  __syncthreads();
  float accq = 0.f;
  for (int e=0;e<EE;e++) accq += s_lnq[e]*Wq[e*EE+tid];
  s_q[tid] = accq;
  __syncthreads();
  // qWkT[h][e=tid]
  for (int h=0; h<HH; h++){
    float a = 0.f;
    #pragma unroll
    for (int dd=0; dd<HDc; dd++) a += s_q[h*HDc+dd]*Wk[tid*EE + h*HDc + dd];
    g_qWkT[h*EE + tid] = a;
  }
  __syncthreads();
  if (tid < HH){
    float a = 0.f;
    for (int e=0;e<EE;e++) a += s_lnk[e]*g_qWkT[tid*EE+e];
    a *= 0.25f;   // 1/sqrt(16)
    float kb = kb2[tid];
    for (int j=0;j<KHc;j++){
      float hv = kb1[j];
      if (hv > 0.f) kb += hv*kW2[j*HH+tid];
    }
    g_dots0[tid] = a + kb;
  }
}

// ---------------- kernel 3: bin points ----------------
__global__ void k_bin(const float* __restrict__ x){
  float mn0=g_min[0], mx0=g_max[0], mn1=g_min[1], mx1=g_max[1];
  float st0 = __fdiv_rn(mx0-mn0, (float)(G1-1));
  float st1 = __fdiv_rn(mx1-mn1, (float)(G2-1));
  for (int i = blockIdx.x*blockDim.x + threadIdx.x; i < BB*NN; i += gridDim.x*blockDim.x){
    float2 v = ((const float2*)x)[i];
    float f0 = rintf(__fdiv_rn(v.x-mn0, st0));
    float f1 = rintf(__fdiv_rn(v.y-mn1, st1));
    f0 = fminf(fmaxf(f0, 0.f), (float)(G1-1));
    f1 = fminf(fmaxf(f1, 0.f), (float)(G2-1));
    int i0 = (int)f0, i1 = (int)f1;
    int b = i / NN, n = i % NN;
    int t = b*MM + i0*G2 + i1;
    int slot = atomicAdd(&g_count[t], 1);
    if (slot < PP) g_ptid[t*PP + slot] = n;
  }
}

// ---------------- kernel 4: main fused kernel (TB tokens per block) ----------------
struct Smem {
  float zk[PP][EE];          // LN'd z of current token's keys
  float qWkT[HH][EE];
  float zbar[TB][HH][EE];    // prob-weighted key aggregates
  float out[TB][EE];
  float znew[TB][EE];
  float ln2[TB][EE];
  float h1[TB][FFc];
  float p[PP+1][HH];         // logits -> probabilities (current token)
  float jx[PP][2];
  float ma[PP+1];
  float lnk[EE];
  float kW1[2][KHc];
  float kb1v[KHc];
  float kW2[KHc][HH];
  float kb2v[HH];
  float dots0[HH];
};

__global__ void __launch_bounds__(128) k_main(
    const float* __restrict__ x, const float* __restrict__ z,
    const float* __restrict__ latent,
    const float* __restrict__ Wv, const float* __restrict__ Wo, const float* __restrict__ bo,
    const float* __restrict__ kW1, const float* __restrict__ kb1,
    const float* __restrict__ kW2, const float* __restrict__ kb2,
    const float* __restrict__ lnk_g, const float* __restrict__ lnk_b,
    const float* __restrict__ ln2_g, const float* __restrict__ ln2_b,
    const float* __restrict__ fW1, const float* __restrict__ fb1,
    const float* __restrict__ fW2, const float* __restrict__ fb2,
    float* __restrict__ out_x, float* __restrict__ out_z)
{
  extern __shared__ Smem S[];
  Smem* s = S;
  int tid = threadIdx.x, lane = tid & 31, warp = tid >> 5;

  // ---- block init: stage constants into smem ----
  {
    float4* dst = (float4*)s->qWkT;
    const float4* src = (const float4*)g_qWkT;
    #pragma unroll
    for (int i = tid; i < HH*EE/4; i += 128) dst[i] = src[i];
    if (tid < EE) s->lnk[tid] = g_lnk[tid];
    if (tid < 2*KHc) ((float*)s->kW1)[tid] = kW1[tid];
    if (tid < KHc) s->kb1v[tid] = kb1[tid];
    if (tid < KHc*HH) ((float*)s->kW2)[tid] = kW2[tid];
    if (tid < HH){ s->kb2v[tid] = kb2[tid]; s->dots0[tid] = g_dots0[tid]; }
  }

  float mn0=g_min[0], mx0=g_max[0], mn1=g_min[1], mx1=g_max[1];
  float st0 = __fdiv_rn(mx0-mn0, (float)(G1-1));
  float st1 = __fdiv_rn(mx1-mn1, (float)(G2-1));

  // preload LN params for gather (feature layout 4*lane..4*lane+3)
  float4 lg = ((const float4*)lnk_g)[lane];
  float4 lb = ((const float4*)lnk_b)[lane];

  int t0 = blockIdx.x * TB;
  int b  = t0 >> 10;        // all TB tokens share batch (TB=8 divides 1024)

  __syncthreads();

  // =========== per-token phases ===========
  for (int tt = 0; tt < TB; tt++){
    int tg = t0 + tt;
    int cell = tg & (MM-1);
    int c1 = cell >> 5, c2 = cell & 31;
    float xg0 = (c1==G1-1) ? mx0 : (mn0 + (float)c1*st0);
    float xg1 = (c2==G2-1) ? mx1 : (mn1 + (float)c2*st1);
    int cnt = g_count[tg]; if (cnt > PP) cnt = PP;

    // ---- A: gather + LayerNorm (one warp per key) ----
    for (int k = warp; k < cnt; k += 4){
      int n = g_ptid[tg*PP + k];
      const float4* zr4 = (const float4*)(z + ((size_t)(b*NN + n))*EE);
      float4 v = zr4[lane];
      float sv = v.x+v.y+v.z+v.w;
      #pragma unroll
      for (int o=16;o;o>>=1) sv += __shfl_xor_sync(0xffffffffu, sv, o);
      float mu = sv*(1.f/EE);
      float d0=v.x-mu, d1=v.y-mu, d2=v.z-mu, d3=v.w-mu;
      float q = d0*d0+d1*d1+d2*d2+d3*d3;
      #pragma unroll
      for (int o=16;o;o>>=1) q += __shfl_xor_sync(0xffffffffu, q, o);
      float rs = rsqrtf(q*(1.f/EE) + 1e-5f);
      float4 outv = make_float4(d0*rs*lg.x+lb.x, d1*rs*lg.y+lb.y,
                                d2*rs*lg.z+lb.z, d3*rs*lg.w+lb.w);
      ((float4*)s->zk[k])[lane] = outv;
      if (lane == 0){
        float2 xv = ((const float2*)x)[(size_t)b*NN + n];
        s->jx[k][0] = xv.x; s->jx[k][1] = xv.y;
      }
    }
    __syncthreads();

    // ---- B: logits + kernel-bias MLP (thread per (k,h)) ----
    for (int pidx = tid; pidx < cnt*HH; pidx += 128){
      int k = pidx >> 3, h = pidx & 7;
      const float4* zk4 = (const float4*)s->zk[k];
      const float4* qw4 = (const float4*)s->qWkT[h];
      float a = 0.f;
      #pragma unroll 8
      for (int i=0;i<EE/4;i++){
        float4 av = zk4[i], bv = qw4[i];
        a += av.x*bv.x + av.y*bv.y + av.z*bv.z + av.w*bv.w;
      }
      a *= 0.25f;
      float dx0 = s->jx[k][0]-xg0, dx1 = s->jx[k][1]-xg1;
      float kb = s->kb2v[h];
      #pragma unroll
      for (int j=0;j<KHc;j++){
        float hv = fmaf(dx0, s->kW1[0][j], fmaf(dx1, s->kW1[1][j], s->kb1v[j]));
        if (hv > 0.f) kb += hv*s->kW2[j][h];
      }
      s->p[k+1][h] = a + kb;
    }
    if (tid < HH) s->p[0][tid] = s->dots0[tid];
    __syncthreads();

    // ---- C: softmax (warp 0), mean-prob + x-update ----
    if (warp == 0){
      int K = cnt + 1;
      if (lane < HH){
        float m = -1e30f;
        for (int k=0;k<K;k++) m = fmaxf(m, s->p[k][lane]);
        float ssum = 0.f;
        for (int k=0;k<K;k++){ float e2 = expf(s->p[k][lane]-m); s->p[k][lane]=e2; ssum += e2; }
        float inv = 1.f/ssum;
        for (int k=0;k<K;k++) s->p[k][lane] *= inv;
      }
      __syncwarp();
      for (int k=lane; k<K; k+=32){
        float4 p0 = ((const float4*)s->p[k])[0];
        float4 p1 = ((const float4*)s->p[k])[1];
        s->ma[k] = 0.125f*(p0.x+p0.y+p0.z+p0.w+p1.x+p1.y+p1.z+p1.w);
      }
      __syncwarp();
      if (lane < 2){
        float acc = s->ma[0]*((lane==0)?xg0:xg1);
        for (int k=0;k<cnt;k++) acc += s->ma[k+1]*s->jx[k][lane];
        out_x[(size_t)tg*2 + lane] = acc;
      }
    }
    __syncthreads();

    // ---- D: zbar[h][e] = sum_k p[h][k]*zk[k][e] (k=0 -> LN(latent)) ----
    {
      float acc[HH];
      float lnkv = s->lnk[tid];
      float4 p0 = ((const float4*)s->p[0])[0];
      float4 p1 = ((const float4*)s->p[0])[1];
      acc[0]=p0.x*lnkv; acc[1]=p0.y*lnkv; acc[2]=p0.z*lnkv; acc[3]=p0.w*lnkv;
      acc[4]=p1.x*lnkv; acc[5]=p1.y*lnkv; acc[6]=p1.z*lnkv; acc[7]=p1.w*lnkv;
      for (int k=0;k<cnt;k++){
        float zkv = s->zk[k][tid];
        float4 q0 = ((const float4*)s->p[k+1])[0];
        float4 q1 = ((const float4*)s->p[k+1])[1];
        acc[0] = fmaf(q0.x, zkv, acc[0]); acc[1] = fmaf(q0.y, zkv, acc[1]);
        acc[2] = fmaf(q0.z, zkv, acc[2]); acc[3] = fmaf(q0.w, zkv, acc[3]);
        acc[4] = fmaf(q1.x, zkv, acc[4]); acc[5] = fmaf(q1.y, zkv, acc[5]);
        acc[6] = fmaf(q1.z, zkv, acc[6]); acc[7] = fmaf(q1.w, zkv, acc[7]);
      }
      #pragma unroll
      for (int h=0;h<HH;h++) s->zbar[tt][h][tid] = acc[h];
    }
    __syncthreads();
  }

  // =========== batched weight passes (amortize L2 over TB tokens) ===========
  int h = tid >> 4;

  // ---- W1: out[t][f] = zbar[t][h(f)] . Wv[:,f] ----
  {
    float acc[TB] = {0,0,0,0,0,0,0,0};
    for (int e0=0; e0<EE; e0+=4){
      float w0 = Wv[(e0+0)*EE+tid];
      float w1 = Wv[(e0+1)*EE+tid];
      float w2 = Wv[(e0+2)*EE+tid];
      float w3 = Wv[(e0+3)*EE+tid];
      #pragma unroll
      for (int t=0;t<TB;t++){
        float4 zb = *(const float4*)&s->zbar[t][h][e0];
        acc[t] += zb.x*w0 + zb.y*w1 + zb.z*w2 + zb.w*w3;
      }
    }
    #pragma unroll
    for (int t=0;t<TB;t++) s->out[t][tid] = acc[t];
  }
  __syncthreads();

  // ---- W2: znew = latent + out @ Wo + bo ----
  {
    float acc[TB] = {0,0,0,0,0,0,0,0};
    for (int f0=0; f0<EE; f0+=4){
      float w0 = Wo[(f0+0)*EE+tid];
      float w1 = Wo[(f0+1)*EE+tid];
      float w2 = Wo[(f0+2)*EE+tid];
      float w3 = Wo[(f0+3)*EE+tid];
      #pragma unroll
      for (int t=0;t<TB;t++){
        float4 o = *(const float4*)&s->out[t][f0];
        acc[t] += o.x*w0 + o.y*w1 + o.z*w2 + o.w*w3;
      }
    }
    float base = latent[tid] + bo[tid];
    #pragma unroll
    for (int t=0;t<TB;t++) s->znew[t][tid] = base + acc[t];
  }
  __syncthreads();

  // ---- LN2 (warp per token, 2 tokens per warp) ----
  {
    float4 g2 = ((const float4*)ln2_g)[lane];
    float4 b2 = ((const float4*)ln2_b)[lane];
    for (int t = warp; t < TB; t += 4){
      float4 v = ((const float4*)s->znew[t])[lane];
      float sv = v.x+v.y+v.z+v.w;
      #pragma unroll
      for (int o=16;o;o>>=1) sv += __shfl_xor_sync(0xffffffffu, sv, o);
      float mu = sv*(1.f/EE);
      float d0=v.x-mu, d1=v.y-mu, d2=v.z-mu, d3=v.w-mu;
      float q = d0*d0+d1*d1+d2*d2+d3*d3;
      #pragma unroll
      for (int o=16;o;o>>=1) q += __shfl_xor_sync(0xffffffffu, q, o);
      float rs = rsqrtf(q*(1.f/EE)+1e-5f);
      ((float4*)s->ln2[t])[lane] = make_float4(d0*rs*g2.x+b2.x, d1*rs*g2.y+b2.y,
                                               d2*rs*g2.z+b2.z, d3*rs*g2.w+b2.w);
    }
  }
  __syncthreads();

  // ---- FFN1: h1 = relu(ln2 @ fW1 + fb1) ----
  {
    float acc[TB] = {0,0,0,0,0,0,0,0};
    for (int e0=0; e0<EE; e0+=4){
      float w0 = fW1[(e0+0)*FFc+tid];
      float w1 = fW1[(e0+1)*FFc+tid];
      float w2 = fW1[(e0+2)*FFc+tid];
      float w3 = fW1[(e0+3)*FFc+tid];
      #pragma unroll
      for (int t=0;t<TB;t++){
        float4 v = *(const float4*)&s->ln2[t][e0];
        acc[t] += v.x*w0 + v.y*w1 + v.z*w2 + v.w*w3;
      }
    }
    float bias = fb1[tid];
    #pragma unroll
    for (int t=0;t<TB;t++) s->h1[t][tid] = fmaxf(acc[t]+bias, 0.f);
  }
  __syncthreads();

  // ---- FFN2: out_z = znew + h1 @ fW2 + fb2 ----
  {
    float acc[TB] = {0,0,0,0,0,0,0,0};
    for (int j0=0; j0<FFc; j0+=4){
      float w0 = fW2[(j0+0)*EE+tid];
      float w1 = fW2[(j0+1)*EE+tid];
      float w2 = fW2[(j0+2)*EE+tid];
      float w3 = fW2[(j0+3)*EE+tid];
      #pragma unroll
      for (int t=0;t<TB;t++){
        float4 v = *(const float4*)&s->h1[t][j0];
        acc[t] += v.x*w0 + v.y*w1 + v.z*w2 + v.w*w3;
      }
    }
    float bias = fb2[tid];
    #pragma unroll
    for (int t=0;t<TB;t++)
      out_z[(size_t)(t0+t)*EE + tid] = s->znew[t][tid] + acc[t] + bias;
  }
}

// ---------------- launch ----------------
extern "C" void kernel_launch(void* const* d_in, const int* in_sizes, int n_in,
                              void* d_out, int out_size){
  const float* x     = (const float*)d_in[0];
  const float* z     = (const float*)d_in[1];
  const float* latent= (const float*)d_in[6];
  const float* Wq    = (const float*)d_in[7];
  const float* Wk    = (const float*)d_in[8];
  const float* Wv    = (const float*)d_in[9];
  const float* Wo    = (const float*)d_in[10];
  const float* bo    = (const float*)d_in[11];
  const float* kW1   = (const float*)d_in[12];
  const float* kb1   = (const float*)d_in[13];
  const float* kW2   = (const float*)d_in[14];
  const float* kb2   = (const float*)d_in[15];
  const float* lnq_g = (const float*)d_in[16];
  const float* lnq_b = (const float*)d_in[17];
  const float* lnk_g = (const float*)d_in[18];
  const float* lnk_b = (const float*)d_in[19];
  const float* ln2_g = (const float*)d_in[20];
  const float* ln2_b = (const float*)d_in[21];
  const float* fW1   = (const float*)d_in[22];
  const float* fb1   = (const float*)d_in[23];
  const float* fW2   = (const float*)d_in[24];
  const float* fb2   = (const float*)d_in[25];

  float* out   = (float*)d_out;
  float* out_x = out;
  float* out_z = out + (size_t)TT*DXc;

  static_assert(sizeof(Smem) < 220*1024, "smem");
  cudaFuncSetAttribute(k_main, cudaFuncAttributeMaxDynamicSharedMemorySize, (int)sizeof(Smem));

  k_init<<<(TT+255)/256, 256>>>();
  k_minmax<<<256, 256>>>(x);
  k_prep<<<1, 128>>>(latent, Wq, Wk, lnq_g, lnq_b, lnk_g, lnk_b, kb1, kW2, kb2);
  k_bin<<<128, 512>>>(x);
  k_main<<<TT/TB, 128, sizeof(Smem)>>>(x, z, latent, Wv, Wo, bo, kW1, kb1, kW2, kb2,
                                       lnk_g, lnk_b, ln2_g, ln2_b, fW1, fb1, fW2, fb2,
                                       out_x, out_z);
}

// round 3
// speedup vs baseline: 3.2362x; 1.8074x over previous
#include <cuda_runtime.h>
#include <math.h>

#define BB 8
#define NN 8192
#define DXc 2
#define EE 128
#define HH 8
#define HDc 16
#define KHc 32
#define FFc 128
#define G1 32
#define G2 32
#define PP 32
#define MM (G1*G2)      // 1024
#define TT (BB*MM)      // 8192
#define TB 8            // tokens per block (one warp per token)

// ---------------- device scratch ----------------
__device__ float g_min[2];
__device__ float g_max[2];
__device__ int   g_count[TT];
__device__ int   g_ptid[TT*PP];
__device__ float g_qWkT[HH*EE];  // [h][e]: q-folded Wk
__device__ float g_lnk[EE];      // LN_k(latent)
__device__ float g_dots0[HH];    // grid-token logit (constant)

// ---------------- helpers ----------------
__device__ __forceinline__ void atomicMinF(float* addr, float v){
  if (v >= 0.f) atomicMin((int*)addr, __float_as_int(v));
  else          atomicMax((unsigned int*)addr, __float_as_uint(v));
}
__device__ __forceinline__ void atomicMaxF(float* addr, float v){
  if (v >= 0.f) atomicMax((int*)addr, __float_as_int(v));
  else          atomicMin((unsigned int*)addr, __float_as_uint(v));
}

// ---------------- kernel 0: init ----------------
__global__ void k_init(){
  int i = blockIdx.x*blockDim.x + threadIdx.x;
  if (i < TT) g_count[i] = 0;
  if (i < 2){
    g_min[i] = __int_as_float(0x7f800000);
    g_max[i] = __int_as_float(0xff800000);
  }
}

// ---------------- kernel 1: global min/max (float4 = 2 points/load) ----------------
__global__ void k_minmax(const float* __restrict__ x){
  float mn0=1e38f, mn1=1e38f, mx0=-1e38f, mx1=-1e38f;
  const float4* x4 = (const float4*)x;
  for (int i = blockIdx.x*blockDim.x + threadIdx.x; i < BB*NN/2; i += gridDim.x*blockDim.x){
    float4 v = x4[i];
    mn0 = fminf(mn0, fminf(v.x, v.z)); mx0 = fmaxf(mx0, fmaxf(v.x, v.z));
    mn1 = fminf(mn1, fminf(v.y, v.w)); mx1 = fmaxf(mx1, fmaxf(v.y, v.w));
  }
  #pragma unroll
  for (int o=16;o;o>>=1){
    mn0 = fminf(mn0, __shfl_xor_sync(0xffffffffu, mn0, o));
    mx0 = fmaxf(mx0, __shfl_xor_sync(0xffffffffu, mx0, o));
    mn1 = fminf(mn1, __shfl_xor_sync(0xffffffffu, mn1, o));
    mx1 = fmaxf(mx1, __shfl_xor_sync(0xffffffffu, mx1, o));
  }
  __shared__ float s[4][8];
  int w = threadIdx.x>>5, l = threadIdx.x&31;
  if (l==0){ s[0][w]=mn0; s[1][w]=mx0; s[2][w]=mn1; s[3][w]=mx1; }
  __syncthreads();
  if (threadIdx.x==0){
    int nw = blockDim.x>>5;
    float a=s[0][0], b=s[1][0], c=s[2][0], d=s[3][0];
    for (int j=1;j<nw;j++){ a=fminf(a,s[0][j]); b=fmaxf(b,s[1][j]); c=fminf(c,s[2][j]); d=fmaxf(d,s[3][j]); }
    atomicMinF(&g_min[0], a); atomicMaxF(&g_max[0], b);
    atomicMinF(&g_min[1], c); atomicMaxF(&g_max[1], d);
  }
}

// ---------------- kernel 2: precompute ----------------
__global__ void k_prep(const float* __restrict__ latent,
                       const float* __restrict__ Wq, const float* __restrict__ Wk,
                       const float* __restrict__ lnq_g, const float* __restrict__ lnq_b,
                       const float* __restrict__ lnk_g, const float* __restrict__ lnk_b,
                       const float* __restrict__ kb1, const float* __restrict__ kW2,
                       const float* __restrict__ kb2){
  __shared__ float s_lnq[EE], s_lnk[EE], s_q[EE], s_red[4];
  int tid = threadIdx.x, lane = tid&31, warp = tid>>5;
  float v = latent[tid];
  float sv = v;
  #pragma unroll
  for (int o=16;o;o>>=1) sv += __shfl_xor_sync(0xffffffffu, sv, o);
  if (lane==0) s_red[warp]=sv;
  __syncthreads();
  float mu = (s_red[0]+s_red[1]+s_red[2]+s_red[3]) * (1.f/EE);
  float d = v - mu;
  float qv = d*d;
  #pragma unroll
  for (int o=16;o;o>>=1) qv += __shfl_xor_sync(0xffffffffu, qv, o);
  __syncthreads();
  if (lane==0) s_red[warp]=qv;
  __syncthreads();
  float var = (s_red[0]+s_red[1]+s_red[2]+s_red[3]) * (1.f/EE);
  float rs = rsqrtf(var + 1e-5f);
  s_lnq[tid] = d*rs*lnq_g[tid] + lnq_b[tid];
  float lk = d*rs*lnk_g[tid] + lnk_b[tid];
  s_lnk[tid] = lk;
  g_lnk[tid] = lk;
  __syncthreads();
  float accq = 0.f;
  for (int e=0;e<EE;e++) accq += s_lnq[e]*Wq[e*EE+tid];
  s_q[tid] = accq;
  __syncthreads();
  for (int h=0; h<HH; h++){
    float a = 0.f;
    #pragma unroll
    for (int dd=0; dd<HDc; dd++) a += s_q[h*HDc+dd]*Wk[tid*EE + h*HDc + dd];
    g_qWkT[h*EE + tid] = a;
  }
  __syncthreads();
  if (tid < HH){
    float a = 0.f;
    for (int e=0;e<EE;e++) a += s_lnk[e]*g_qWkT[tid*EE+e];
    a *= 0.25f;
    float kb = kb2[tid];
    for (int j=0;j<KHc;j++){
      float hv = kb1[j];
      if (hv > 0.f) kb += hv*kW2[j*HH+tid];
    }
    g_dots0[tid] = a + kb;
  }
}

// ---------------- kernel 3: bin points (2 points/thread) ----------------
__global__ void k_bin(const float* __restrict__ x){
  float mn0=g_min[0], mx0=g_max[0], mn1=g_min[1], mx1=g_max[1];
  float st0 = __fdiv_rn(mx0-mn0, (float)(G1-1));
  float st1 = __fdiv_rn(mx1-mn1, (float)(G2-1));
  const float4* x4 = (const float4*)x;
  for (int i = blockIdx.x*blockDim.x + threadIdx.x; i < BB*NN/2; i += gridDim.x*blockDim.x){
    float4 v = x4[i];
    #pragma unroll
    for (int u=0;u<2;u++){
      float px = u ? v.z : v.x;
      float py = u ? v.w : v.y;
      float f0 = rintf(__fdiv_rn(px-mn0, st0));
      float f1 = rintf(__fdiv_rn(py-mn1, st1));
      f0 = fminf(fmaxf(f0, 0.f), (float)(G1-1));
      f1 = fminf(fmaxf(f1, 0.f), (float)(G2-1));
      int p = 2*i + u;
      int b = p / NN, n = p % NN;
      int t = b*MM + ((int)f0)*G2 + (int)f1;
      int slot = atomicAdd(&g_count[t], 1);
      if (slot < PP) g_ptid[t*PP + slot] = n;
    }
  }
}

// ---------------- kernel 4: main fused kernel ----------------
struct Smem {
  float zbar[TB][HH][EE];   // 32KB
  float out[TB][EE];
  float znew[TB][EE];
  float ln2[TB][EE];
  float h1[TB][FFc];
  float p[TB][PP+2][HH];    // logits/probs per token (slot 0 = grid token)
};

__global__ void __launch_bounds__(256, 3) k_main(
    const float* __restrict__ x, const float* __restrict__ z,
    const float* __restrict__ latent,
    const float* __restrict__ Wv, const float* __restrict__ Wo, const float* __restrict__ bo,
    const float* __restrict__ kW1, const float* __restrict__ kb1,
    const float* __restrict__ kW2, const float* __restrict__ kb2,
    const float* __restrict__ lnk_g, const float* __restrict__ lnk_b,
    const float* __restrict__ ln2_g, const float* __restrict__ ln2_b,
    const float* __restrict__ fW1, const float* __restrict__ fb1,
    const float* __restrict__ fW2, const float* __restrict__ fb2,
    float* __restrict__ out_x, float* __restrict__ out_z)
{
  extern __shared__ Smem S[];
  Smem* s = S;
  int tid = threadIdx.x, lane = tid & 31, warp = tid >> 5;
  int t0 = blockIdx.x * TB;
  int b  = t0 >> 10;

  float mn0=g_min[0], mx0=g_max[0], mn1=g_min[1], mx1=g_max[1];
  float st0 = __fdiv_rn(mx0-mn0, (float)(G1-1));
  float st1 = __fdiv_rn(mx1-mn1, (float)(G2-1));

  // ============ token phase: warp `warp` owns token t0+warp ============
  {
    int tg = t0 + warp;
    int cell = tg & (MM-1);
    int c1 = cell >> 5, c2 = cell & 31;
    float xg0 = (c1==G1-1) ? mx0 : (mn0 + (float)c1*st0);
    float xg1 = (c2==G2-1) ? mx1 : (mn1 + (float)c2*st1);
    int cnt = g_count[tg]; if (cnt > PP) cnt = PP;

    // prefetch key ids + coords (lane k holds key k)
    int nid = 0; float2 xv = make_float2(0.f, 0.f);
    if (lane < cnt){
      nid = g_ptid[tg*PP + lane];
      xv = ((const float2*)x)[(size_t)b*NN + nid];
    }

    // constants in registers
    float4 qw[HH];
    #pragma unroll
    for (int h=0;h<HH;h++) qw[h] = ((const float4*)(g_qWkT + h*EE))[lane];
    float kw1a = kW1[lane], kw1b = kW1[KHc+lane], kb1r = kb1[lane];
    float4 kw2a = ((const float4*)kW2)[lane*2];
    float4 kw2b = ((const float4*)kW2)[lane*2+1];
    float4 lg = ((const float4*)lnk_g)[lane];
    float4 lb = ((const float4*)lnk_b)[lane];

    // ---- pass 1: logits ----
    for (int k=0;k<cnt;k++){
      int n = __shfl_sync(0xffffffffu, nid, k);
      float dx0 = __shfl_sync(0xffffffffu, xv.x, k) - xg0;
      float dx1 = __shfl_sync(0xffffffffu, xv.y, k) - xg1;
      float4 v = ((const float4*)(z + (size_t)(b*NN+n)*EE))[lane];
      float sv = v.x+v.y+v.z+v.w;
      #pragma unroll
      for (int o=16;o;o>>=1) sv += __shfl_xor_sync(0xffffffffu, sv, o);
      float mu = sv*(1.f/EE);
      float d0=v.x-mu, d1=v.y-mu, d2=v.z-mu, d3=v.w-mu;
      float q = d0*d0+d1*d1+d2*d2+d3*d3;
      #pragma unroll
      for (int o=16;o;o>>=1) q += __shfl_xor_sync(0xffffffffu, q, o);
      float rs = rsqrtf(q*(1.f/EE) + 1e-5f);
      float z0=d0*rs*lg.x+lb.x, z1=d1*rs*lg.y+lb.y, z2=d2*rs*lg.z+lb.z, z3=d3*rs*lg.w+lb.w;
      float p[HH];
      #pragma unroll
      for (int h=0;h<HH;h++)
        p[h] = 0.25f*(z0*qw[h].x + z1*qw[h].y + z2*qw[h].z + z3*qw[h].w);
      float hv = fmaxf(fmaf(dx0,kw1a,fmaf(dx1,kw1b,kb1r)), 0.f);
      p[0]=fmaf(hv,kw2a.x,p[0]); p[1]=fmaf(hv,kw2a.y,p[1]);
      p[2]=fmaf(hv,kw2a.z,p[2]); p[3]=fmaf(hv,kw2a.w,p[3]);
      p[4]=fmaf(hv,kw2b.x,p[4]); p[5]=fmaf(hv,kw2b.y,p[5]);
      p[6]=fmaf(hv,kw2b.z,p[6]); p[7]=fmaf(hv,kw2b.w,p[7]);
      #pragma unroll
      for (int o=16;o;o>>=1){
        #pragma unroll
        for (int h=0;h<HH;h++) p[h] += __shfl_xor_sync(0xffffffffu, p[h], o);
      }
      if (lane < HH) s->p[warp][k+1][lane] = p[lane];
    }
    if (lane < HH) s->p[warp][0][lane] = g_dots0[lane];
    __syncwarp();

    // ---- softmax (lanes 0..7 = heads) ----
    int K = cnt + 1;
    if (lane < HH){
      float m = -1e30f;
      for (int k=0;k<K;k++) m = fmaxf(m, s->p[warp][k][lane]);
      float ss = 0.f;
      for (int k=0;k<K;k++){
        float e2 = expf(s->p[warp][k][lane] - m);
        s->p[warp][k][lane] = e2; ss += e2;
      }
      float inv = 1.f/ss;
      for (int k=0;k<K;k++) s->p[warp][k][lane] *= inv;
    }
    __syncwarp();

    // ---- TE x-update ----
    {
      float c0=0.f, c1=0.f;
      if (lane < cnt){
        float4 pa = *(const float4*)&s->p[warp][lane+1][0];
        float4 pb = *(const float4*)&s->p[warp][lane+1][4];
        float ma = 0.125f*(pa.x+pa.y+pa.z+pa.w+pb.x+pb.y+pb.z+pb.w);
        c0 = ma*xv.x; c1 = ma*xv.y;
      }
      if (lane == 0){
        float4 pa = *(const float4*)&s->p[warp][0][0];
        float4 pb = *(const float4*)&s->p[warp][0][4];
        float ma = 0.125f*(pa.x+pa.y+pa.z+pa.w+pb.x+pb.y+pb.z+pb.w);
        c0 += ma*xg0; c1 += ma*xg1;
      }
      #pragma unroll
      for (int o=16;o;o>>=1){
        c0 += __shfl_xor_sync(0xffffffffu, c0, o);
        c1 += __shfl_xor_sync(0xffffffffu, c1, o);
      }
      if (lane == 0){
        out_x[(size_t)tg*2]   = c0;
        out_x[(size_t)tg*2+1] = c1;
      }
    }

    // ---- pass 2: zbar accumulation (re-read z, L1-hot) ----
    {
      float4 lnkv = ((const float4*)g_lnk)[lane];
      float4 p0a = *(const float4*)&s->p[warp][0][0];
      float4 p0b = *(const float4*)&s->p[warp][0][4];
      float4 acc[HH];
      acc[0]=make_float4(p0a.x*lnkv.x,p0a.x*lnkv.y,p0a.x*lnkv.z,p0a.x*lnkv.w);
      acc[1]=make_float4(p0a.y*lnkv.x,p0a.y*lnkv.y,p0a.y*lnkv.z,p0a.y*lnkv.w);
      acc[2]=make_float4(p0a.z*lnkv.x,p0a.z*lnkv.y,p0a.z*lnkv.z,p0a.z*lnkv.w);
      acc[3]=make_float4(p0a.w*lnkv.x,p0a.w*lnkv.y,p0a.w*lnkv.z,p0a.w*lnkv.w);
      acc[4]=make_float4(p0b.x*lnkv.x,p0b.x*lnkv.y,p0b.x*lnkv.z,p0b.x*lnkv.w);
      acc[5]=make_float4(p0b.y*lnkv.x,p0b.y*lnkv.y,p0b.y*lnkv.z,p0b.y*lnkv.w);
      acc[6]=make_float4(p0b.z*lnkv.x,p0b.z*lnkv.y,p0b.z*lnkv.z,p0b.z*lnkv.w);
      acc[7]=make_float4(p0b.w*lnkv.x,p0b.w*lnkv.y,p0b.w*lnkv.z,p0b.w*lnkv.w);
      for (int k=0;k<cnt;k++){
        int n = __shfl_sync(0xffffffffu, nid, k);
        float4 v = ((const float4*)(z + (size_t)(b*NN+n)*EE))[lane];
        float sv = v.x+v.y+v.z+v.w;
        #pragma unroll
        for (int o=16;o;o>>=1) sv += __shfl_xor_sync(0xffffffffu, sv, o);
        float mu = sv*(1.f/EE);
        float d0=v.x-mu, d1=v.y-mu, d2=v.z-mu, d3=v.w-mu;
        float q = d0*d0+d1*d1+d2*d2+d3*d3;
        #pragma unroll
        for (int o=16;o;o>>=1) q += __shfl_xor_sync(0xffffffffu, q, o);
        float rs = rsqrtf(q*(1.f/EE) + 1e-5f);
        float z0=d0*rs*lg.x+lb.x, z1=d1*rs*lg.y+lb.y, z2=d2*rs*lg.z+lb.z, z3=d3*rs*lg.w+lb.w;
        float4 pa = *(const float4*)&s->p[warp][k+1][0];
        float4 pb = *(const float4*)&s->p[warp][k+1][4];
        float pk[HH] = {pa.x,pa.y,pa.z,pa.w,pb.x,pb.y,pb.z,pb.w};
        #pragma unroll
        for (int h=0;h<HH;h++){
          acc[h].x = fmaf(pk[h], z0, acc[h].x);
          acc[h].y = fmaf(pk[h], z1, acc[h].y);
          acc[h].z = fmaf(pk[h], z2, acc[h].z);
          acc[h].w = fmaf(pk[h], z3, acc[h].w);
        }
      }
      #pragma unroll
      for (int h=0;h<HH;h++)
        ((float4*)s->zbar[warp][h])[lane] = acc[h];
    }
  }
  __syncthreads();

  // ============ weight passes: thread = (g, f), 4 tokens each ============
  int f = tid & 127;
  int g = tid >> 7;
  int h = f >> 4;
  int tb0 = g*4;

  // ---- W1: out = zbar . Wv ----
  {
    float acc[4] = {0,0,0,0};
    for (int e0=0; e0<EE; e0+=4){
      float w0 = Wv[(e0+0)*EE+f];
      float w1 = Wv[(e0+1)*EE+f];
      float w2 = Wv[(e0+2)*EE+f];
      float w3 = Wv[(e0+3)*EE+f];
      #pragma unroll
      for (int i=0;i<4;i++){
        float4 zb = *(const float4*)&s->zbar[tb0+i][h][e0];
        acc[i] += zb.x*w0 + zb.y*w1 + zb.z*w2 + zb.w*w3;
      }
    }
    #pragma unroll
    for (int i=0;i<4;i++) s->out[tb0+i][f] = acc[i];
  }
  __syncthreads();

  // ---- W2: znew = latent + out @ Wo + bo ----
  {
    float acc[4] = {0,0,0,0};
    for (int f0=0; f0<EE; f0+=4){
      float w0 = Wo[(f0+0)*EE+f];
      float w1 = Wo[(f0+1)*EE+f];
      float w2 = Wo[(f0+2)*EE+f];
      float w3 = Wo[(f0+3)*EE+f];
      #pragma unroll
      for (int i=0;i<4;i++){
        float4 o4 = *(const float4*)&s->out[tb0+i][f0];
        acc[i] += o4.x*w0 + o4.y*w1 + o4.z*w2 + o4.w*w3;
      }
    }
    float base = latent[f] + bo[f];
    #pragma unroll
    for (int i=0;i<4;i++) s->znew[tb0+i][f] = base + acc[i];
  }
  __syncthreads();

  // ---- LN2: warp per token ----
  {
    float4 g2 = ((const float4*)ln2_g)[lane];
    float4 b2 = ((const float4*)ln2_b)[lane];
    int t = warp;
    float4 v = ((const float4*)s->znew[t])[lane];
    float sv = v.x+v.y+v.z+v.w;
    #pragma unroll
    for (int o=16;o;o>>=1) sv += __shfl_xor_sync(0xffffffffu, sv, o);
    float mu = sv*(1.f/EE);
    float d0=v.x-mu, d1=v.y-mu, d2=v.z-mu, d3=v.w-mu;
    float q = d0*d0+d1*d1+d2*d2+d3*d3;
    #pragma unroll
    for (int o=16;o;o>>=1) q += __shfl_xor_sync(0xffffffffu, q, o);
    float rs = rsqrtf(q*(1.f/EE)+1e-5f);
    ((float4*)s->ln2[t])[lane] = make_float4(d0*rs*g2.x+b2.x, d1*rs*g2.y+b2.y,
                                             d2*rs*g2.z+b2.z, d3*rs*g2.w+b2.w);
  }
  __syncthreads();

  // ---- FFN1 ----
  {
    float acc[4] = {0,0,0,0};
    for (int e0=0; e0<EE; e0+=4){
      float w0 = fW1[(e0+0)*FFc+f];
      float w1 = fW1[(e0+1)*FFc+f];
      float w2 = fW1[(e0+2)*FFc+f];
      float w3 = fW1[(e0+3)*FFc+f];
      #pragma unroll
      for (int i=0;i<4;i++){
        float4 v = *(const float4*)&s->ln2[tb0+i][e0];
        acc[i] += v.x*w0 + v.y*w1 + v.z*w2 + v.w*w3;
      }
    }
    float bias = fb1[f];
    #pragma unroll
    for (int i=0;i<4;i++) s->h1[tb0+i][f] = fmaxf(acc[i]+bias, 0.f);
  }
  __syncthreads();

  // ---- FFN2 + residual ----
  {
    float acc[4] = {0,0,0,0};
    for (int j0=0; j0<FFc; j0+=4){
      float w0 = fW2[(j0+0)*EE+f];
      float w1 = fW2[(j0+1)*EE+f];
      float w2 = fW2[(j0+2)*EE+f];
      float w3 = fW2[(j0+3)*EE+f];
      #pragma unroll
      for (int i=0;i<4;i++){
        float4 v = *(const float4*)&s->h1[tb0+i][j0];
        acc[i] += v.x*w0 + v.y*w1 + v.z*w2 + v.w*w3;
      }
    }
    float bias = fb2[f];
    #pragma unroll
    for (int i=0;i<4;i++)
      out_z[(size_t)(t0+tb0+i)*EE + f] = s->znew[tb0+i][f] + acc[i] + bias;
  }
}

// ---------------- launch ----------------
extern "C" void kernel_launch(void* const* d_in, const int* in_sizes, int n_in,
                              void* d_out, int out_size){
  const float* x     = (const float*)d_in[0];
  const float* z     = (const float*)d_in[1];
  const float* latent= (const float*)d_in[6];
  const float* Wq    = (const float*)d_in[7];
  const float* Wk    = (const float*)d_in[8];
  const float* Wv    = (const float*)d_in[9];
  const float* Wo    = (const float*)d_in[10];
  const float* bo    = (const float*)d_in[11];
  const float* kW1   = (const float*)d_in[12];
  const float* kb1   = (const float*)d_in[13];
  const float* kW2   = (const float*)d_in[14];
  const float* kb2   = (const float*)d_in[15];
  const float* lnq_g = (const float*)d_in[16];
  const float* lnq_b = (const float*)d_in[17];
  const float* lnk_g = (const float*)d_in[18];
  const float* lnk_b = (const float*)d_in[19];
  const float* ln2_g = (const float*)d_in[20];
  const float* ln2_b = (const float*)d_in[21];
  const float* fW1   = (const float*)d_in[22];
  const float* fb1   = (const float*)d_in[23];
  const float* fW2   = (const float*)d_in[24];
  const float* fb2   = (const float*)d_in[25];

  float* out   = (float*)d_out;
  float* out_x = out;
  float* out_z = out + (size_t)TT*DXc;

  static_assert(sizeof(Smem) < 75*1024, "smem");
  cudaFuncSetAttribute(k_main, cudaFuncAttributeMaxDynamicSharedMemorySize, (int)sizeof(Smem));

  k_init<<<(TT+255)/256, 256>>>();
  k_minmax<<<128, 256>>>(x);
  k_prep<<<1, 128>>>(latent, Wq, Wk, lnq_g, lnq_b, lnk_g, lnk_b, kb1, kW2, kb2);
  k_bin<<<128, 256>>>(x);
  k_main<<<TT/TB, 256, sizeof(Smem)>>>(x, z, latent, Wv, Wo, bo, kW1, kb1, kW2, kb2,
                                       lnk_g, lnk_b, ln2_g, ln2_b, fW1, fb1, fW2, fb2,
                                       out_x, out_z);
}